// round 1
// baseline (speedup 1.0000x reference)
#include <cuda_runtime.h>
#include <math.h>

// Problem constants
#define NB   4
#define SEQ  2048
#define DIM  512
#define NH   8
#define DHD  64
#define MROWS (NB * SEQ)   // 8192

// Scratch (allocation-free rule: __device__ globals)
__device__ float g_q[MROWS * DIM];
__device__ float g_k[MROWS * DIM];
__device__ float g_v[MROWS * DIM];
__device__ float g_att[MROWS * DIM];

// ---------------------------------------------------------------------------
// Shared GEMM body: C[128x128 tile] = A[M,512] @ W[512,512] + bias
// Block: 256 threads, 8x8 micro-tile per thread, K-step 8.
// ---------------------------------------------------------------------------
__device__ __forceinline__ void gemm512_body(
    const float* __restrict__ A, const float* __restrict__ W,
    const float* __restrict__ bias, float* __restrict__ C)
{
    __shared__ float As[8][128];
    __shared__ float Bs[8][128];

    const int tid = threadIdx.x;
    const int bm  = blockIdx.y * 128;
    const int bn  = blockIdx.x * 128;
    const int tm  = (tid >> 4) * 8;    // 0..120
    const int tn  = (tid & 15) * 8;    // 0..120

    const int arow = tid >> 1;         // 0..127
    const int acol = (tid & 1) * 4;    // 0 or 4
    const int brow = tid >> 5;         // 0..7
    const int bcol = (tid & 31) * 4;   // 0..124

    float acc[8][8];
#pragma unroll
    for (int i = 0; i < 8; ++i)
#pragma unroll
        for (int j = 0; j < 8; ++j) acc[i][j] = 0.f;

    const float* Ap = A + (bm + arow) * DIM + acol;
    const float* Wp = W + brow * DIM + bn + bcol;

    for (int k0 = 0; k0 < DIM; k0 += 8) {
        float4 a = *(const float4*)Ap; Ap += 8;
        float4 b = *(const float4*)Wp; Wp += 8 * DIM;

        As[acol + 0][arow] = a.x;
        As[acol + 1][arow] = a.y;
        As[acol + 2][arow] = a.z;
        As[acol + 3][arow] = a.w;
        *(float4*)&Bs[brow][bcol] = b;
        __syncthreads();

#pragma unroll
        for (int kk = 0; kk < 8; ++kk) {
            float ar[8], br[8];
            *(float4*)(ar)     = *(const float4*)&As[kk][tm];
            *(float4*)(ar + 4) = *(const float4*)&As[kk][tm + 4];
            *(float4*)(br)     = *(const float4*)&Bs[kk][tn];
            *(float4*)(br + 4) = *(const float4*)&Bs[kk][tn + 4];
#pragma unroll
            for (int i = 0; i < 8; ++i)
#pragma unroll
                for (int j = 0; j < 8; ++j)
                    acc[i][j] = fmaf(ar[i], br[j], acc[i][j]);
        }
        __syncthreads();
    }

#pragma unroll
    for (int i = 0; i < 8; ++i) {
#pragma unroll
        for (int j4 = 0; j4 < 2; ++j4) {
            float4 o;
            o.x = acc[i][j4 * 4 + 0] + bias[bn + tn + j4 * 4 + 0];
            o.y = acc[i][j4 * 4 + 1] + bias[bn + tn + j4 * 4 + 1];
            o.z = acc[i][j4 * 4 + 2] + bias[bn + tn + j4 * 4 + 2];
            o.w = acc[i][j4 * 4 + 3] + bias[bn + tn + j4 * 4 + 3];
            *(float4*)&C[(bm + tm + i) * DIM + bn + tn + j4 * 4] = o;
        }
    }
}

// Fused QKV projection: grid.z picks which projection this block computes.
__global__ __launch_bounds__(256) void qkv_kernel(
    const float* __restrict__ x,
    const float* __restrict__ Wq, const float* __restrict__ bq,
    const float* __restrict__ Wk, const float* __restrict__ bk,
    const float* __restrict__ Wv, const float* __restrict__ bv)
{
    const float* W; const float* bias; float* C;
    if (blockIdx.z == 0)      { W = Wq; bias = bq; C = g_q; }
    else if (blockIdx.z == 1) { W = Wk; bias = bk; C = g_k; }
    else                      { W = Wv; bias = bv; C = g_v; }
    gemm512_body(x, W, bias, C);
}

// Output projection: d_out = g_att @ Wh + bh
__global__ __launch_bounds__(256) void outproj_kernel(
    const float* __restrict__ Wh, const float* __restrict__ bh,
    float* __restrict__ out)
{
    gemm512_body(g_att, Wh, bh, out);
}

// ---------------------------------------------------------------------------
// Flash-style attention. One block = one (b, h, 64-query tile).
// 256 threads; thread t owns query row r = t/4 and interleaved cols
// c = (t&3) + 4*j, j=0..15 (conflict-free k reads across the quad).
// ---------------------------------------------------------------------------
#define PITCH 68
#define SMEM_ATTN (3 * 64 * PITCH * 4)

__global__ __launch_bounds__(256) void attn_kernel()
{
    extern __shared__ float sm[];
    float* qp = sm;                  // [64][PITCH]  (q staging, then p tile)
    float* ks = sm + 64 * PITCH;     // [64][PITCH]
    float* vs = sm + 2 * 64 * PITCH; // [64][PITCH]

    const int tid = threadIdx.x;
    const int b  = blockIdx.z;
    const int h  = blockIdx.y;
    const int qt = blockIdx.x;
    const int r  = tid >> 2;   // query row in tile
    const int cq = tid & 3;    // quad lane

    const float* qg = g_q + ((size_t)(b * SEQ + qt * 64)) * DIM + h * DHD;
    const float* kb = g_k + ((size_t)(b * SEQ)) * DIM + h * DHD;
    const float* vb = g_v + ((size_t)(b * SEQ)) * DIM + h * DHD;

    // Stage q tile -> smem (coalesced), scaled by 1/sqrt(d_head)
#pragma unroll
    for (int t = 0; t < 4; ++t) {
        int idx = tid + t * 256;           // 0..1023
        int row = idx >> 4, c4 = idx & 15;
        float4 v = *(const float4*)(qg + row * DIM + c4 * 4);
        v.x *= 0.125f; v.y *= 0.125f; v.z *= 0.125f; v.w *= 0.125f;
        *(float4*)&qp[row * PITCH + c4 * 4] = v;
    }
    __syncthreads();

    // Pull this thread's full q row into registers (quad-broadcast reads)
    float qr[64];
#pragma unroll
    for (int d4 = 0; d4 < 16; ++d4) {
        float4 v = *(const float4*)&qp[r * PITCH + d4 * 4];
        qr[4 * d4 + 0] = v.x; qr[4 * d4 + 1] = v.y;
        qr[4 * d4 + 2] = v.z; qr[4 * d4 + 3] = v.w;
    }
    __syncthreads();   // everyone done reading q; qp reusable as p-tile

    float m = -1e30f, l = 0.f;
    float acc[16];
#pragma unroll
    for (int j = 0; j < 16; ++j) acc[j] = 0.f;

    for (int kt = 0; kt < SEQ / 64; ++kt) {
        const float* kg = kb + (size_t)kt * 64 * DIM;
        const float* vg = vb + (size_t)kt * 64 * DIM;
#pragma unroll
        for (int t = 0; t < 4; ++t) {
            int idx = tid + t * 256;
            int row = idx >> 4, c4 = idx & 15;
            *(float4*)&ks[row * PITCH + c4 * 4] = *(const float4*)(kg + row * DIM + c4 * 4);
            *(float4*)&vs[row * PITCH + c4 * 4] = *(const float4*)(vg + row * DIM + c4 * 4);
        }
        __syncthreads();

        // s[r][c] for c = cq + 4j
        float sv[16];
#pragma unroll
        for (int j = 0; j < 16; ++j) {
            const int c = cq + 4 * j;
            const float* krow = &ks[c * PITCH];
            float dot = 0.f;
#pragma unroll
            for (int d4 = 0; d4 < 16; ++d4) {
                float4 kv = *(const float4*)(krow + d4 * 4);
                dot = fmaf(qr[4 * d4 + 0], kv.x, dot);
                dot = fmaf(qr[4 * d4 + 1], kv.y, dot);
                dot = fmaf(qr[4 * d4 + 2], kv.z, dot);
                dot = fmaf(qr[4 * d4 + 3], kv.w, dot);
            }
            sv[j] = dot;
        }

        // Online softmax (row spread across the 4-lane quad)
        float ml = sv[0];
#pragma unroll
        for (int j = 1; j < 16; ++j) ml = fmaxf(ml, sv[j]);
        ml = fmaxf(ml, __shfl_xor_sync(0xffffffffu, ml, 1));
        ml = fmaxf(ml, __shfl_xor_sync(0xffffffffu, ml, 2));
        const float mnew = fmaxf(m, ml);
        const float corr = __expf(m - mnew);
        float ls = 0.f;
#pragma unroll
        for (int j = 0; j < 16; ++j) {
            sv[j] = __expf(sv[j] - mnew);
            ls += sv[j];
        }
        ls += __shfl_xor_sync(0xffffffffu, ls, 1);
        ls += __shfl_xor_sync(0xffffffffu, ls, 2);
        l = l * corr + ls;
        m = mnew;
#pragma unroll
        for (int j = 0; j < 16; ++j) acc[j] *= corr;

        // publish p
#pragma unroll
        for (int j = 0; j < 16; ++j)
            qp[r * PITCH + cq + 4 * j] = sv[j];
        __syncthreads();

        // acc[cd] += sum_c p[r][c] * v[c][cd],  cd = cq + 4j
#pragma unroll 4
        for (int c = 0; c < 64; ++c) {
            const float p = qp[r * PITCH + c];
            const float* vrow = vs + c * PITCH + cq;
#pragma unroll
            for (int j = 0; j < 16; ++j)
                acc[j] = fmaf(p, vrow[4 * j], acc[j]);
        }
        __syncthreads();   // protect ks/vs/qp before next iteration overwrites
    }

    const float inv = 1.f / l;
    float* og = g_att + ((size_t)(b * SEQ + qt * 64 + r)) * DIM + h * DHD;
#pragma unroll
    for (int j = 0; j < 16; ++j)
        og[cq + 4 * j] = acc[j] * inv;
}

// ---------------------------------------------------------------------------
extern "C" void kernel_launch(void* const* d_in, const int* in_sizes, int n_in,
                              void* d_out, int out_size)
{
    const float* x  = (const float*)d_in[0];
    const float* Wq = (const float*)d_in[1];
    const float* bq = (const float*)d_in[2];
    const float* Wk = (const float*)d_in[3];
    const float* bk = (const float*)d_in[4];
    const float* Wv = (const float*)d_in[5];
    const float* bv = (const float*)d_in[6];
    const float* Wh = (const float*)d_in[7];
    const float* bh = (const float*)d_in[8];
    float* out = (float*)d_out;

    cudaFuncSetAttribute(attn_kernel,
                         cudaFuncAttributeMaxDynamicSharedMemorySize, SMEM_ATTN);

    // 1. QKV projections (fused across grid.z)
    qkv_kernel<<<dim3(DIM / 128, MROWS / 128, 3), 256>>>(x, Wq, bq, Wk, bk, Wv, bv);

    // 2. Flash attention per (query-tile, head, batch)
    attn_kernel<<<dim3(SEQ / 64, NH, NB), 256, SMEM_ATTN>>>();

    // 3. Output projection
    outproj_kernel<<<dim3(DIM / 128, MROWS / 128, 1), 256>>>(Wh, bh, out);
}

// round 3
// speedup vs baseline: 5.9737x; 5.9737x over previous
#include <cuda_runtime.h>
#include <cstdint>

#define NB   4
#define SEQ  2048
#define DIM  512
#define NH   8
#define DHD  64

// Scratch (__device__ globals; allocation-free rule)
__device__ float g_q  [(size_t)NB*NH*SEQ*DHD];   // [b,h,s,d] 16 MB
__device__ float g_k  [(size_t)NB*NH*SEQ*DHD];   // [b,h,s,d] 16 MB
__device__ float g_v  [(size_t)NB*NH*SEQ*DHD];   // [b,h,s,d] 16 MB
__device__ float g_att[(size_t)NB*SEQ*DIM];      // [b*s,512] 16 MB

__device__ __forceinline__ uint32_t f2tf(float x) {
    uint32_t u; asm("cvt.rna.tf32.f32 %0, %1;" : "=r"(u) : "f"(x)); return u;
}

// D += A(m16k8) * B(k8n8), tf32 inputs, f32 accum
__device__ __forceinline__ void mma8(float c[4], const uint32_t a[4], const uint32_t b[2]) {
    asm volatile(
        "mma.sync.aligned.m16n8k8.row.col.f32.tf32.tf32.f32 "
        "{%0,%1,%2,%3}, {%4,%5,%6,%7}, {%8,%9}, {%0,%1,%2,%3};"
        : "+f"(c[0]), "+f"(c[1]), "+f"(c[2]), "+f"(c[3])
        : "r"(a[0]), "r"(a[1]), "r"(a[2]), "r"(a[3]), "r"(b[0]), "r"(b[1]));
}

#define PA 132   // pitch (floats) for [k][m] / [k][n] tiles; 132%32=4 -> conflict-free frags

// ---------------------------------------------------------------------------
// GEMM body: C = A[8192,512] @ W[512,512] + bias
// MODE 0: store to [b,h,s,d] scratch; MODE 1: plain [m,512]
// Block 128x128, 8 warps (4m x 2n), warp tile 32x64, K-chunk 32.
// ---------------------------------------------------------------------------
template<int MODE>
__device__ __forceinline__ void gemm_body(
    const float* __restrict__ A, const float* __restrict__ W,
    const float* __restrict__ bias, float* __restrict__ dst)
{
    __shared__ uint32_t As[32][PA];   // [k][m]
    __shared__ uint32_t Bs[32][PA];   // [k][n]
    const int tid = threadIdx.x;
    const int w = tid >> 5, t4 = tid & 3, tg = (tid & 31) >> 2;
    const int wm = (w & 3) * 32, wn = (w >> 2) * 64;
    const int bm = blockIdx.y * 128, bn = blockIdx.x * 128;

    float acc[2][8][4];
#pragma unroll
    for (int mb = 0; mb < 2; ++mb)
#pragma unroll
        for (int nb = 0; nb < 8; ++nb)
#pragma unroll
            for (int i = 0; i < 4; ++i) acc[mb][nb][i] = 0.f;

    for (int kc = 0; kc < 16; ++kc) {
#pragma unroll
        for (int i = 0; i < 4; ++i) {
            int lin = tid + i * 256;                 // 1024 = 128 rows x 8 f4
            int row = lin >> 3, kq = (lin & 7) << 2;
            float4 v = *(const float4*)(A + (size_t)(bm + row) * DIM + kc * 32 + kq);
            As[kq + 0][row] = f2tf(v.x); As[kq + 1][row] = f2tf(v.y);
            As[kq + 2][row] = f2tf(v.z); As[kq + 3][row] = f2tf(v.w);
        }
#pragma unroll
        for (int i = 0; i < 4; ++i) {
            int lin = tid + i * 256;                 // 1024 = 32 k x 32 f4
            int kr = lin >> 5, c4 = (lin & 31) << 2;
            float4 v = *(const float4*)(W + (size_t)(kc * 32 + kr) * DIM + bn + c4);
            uint4 u; u.x = f2tf(v.x); u.y = f2tf(v.y); u.z = f2tf(v.z); u.w = f2tf(v.w);
            *(uint4*)&Bs[kr][c4] = u;
        }
        __syncthreads();

#pragma unroll
        for (int ks = 0; ks < 4; ++ks) {
            const int k8 = ks * 8;
            uint32_t a[2][4];
#pragma unroll
            for (int mb = 0; mb < 2; ++mb) {
                const int m0 = wm + mb * 16 + tg;
                a[mb][0] = As[k8 + t4][m0];
                a[mb][1] = As[k8 + t4][m0 + 8];
                a[mb][2] = As[k8 + t4 + 4][m0];
                a[mb][3] = As[k8 + t4 + 4][m0 + 8];
            }
#pragma unroll
            for (int nb = 0; nb < 8; ++nb) {
                uint32_t bf[2];
                const int n0 = wn + nb * 8 + tg;
                bf[0] = Bs[k8 + t4][n0];
                bf[1] = Bs[k8 + t4 + 4][n0];
                mma8(acc[0][nb], a[0], bf);
                mma8(acc[1][nb], a[1], bf);
            }
        }
        __syncthreads();
    }

#pragma unroll
    for (int mb = 0; mb < 2; ++mb)
#pragma unroll
        for (int nb = 0; nb < 8; ++nb)
#pragma unroll
            for (int half = 0; half < 2; ++half) {
                const int m = bm + wm + mb * 16 + tg + half * 8;
                const int n = bn + wn + nb * 8 + 2 * t4;
                float2 o;
                o.x = acc[mb][nb][half * 2 + 0] + bias[n];
                o.y = acc[mb][nb][half * 2 + 1] + bias[n + 1];
                if (MODE == 1) {
                    *(float2*)(dst + (size_t)m * DIM + n) = o;
                } else {
                    const int b = m >> 11, s = m & (SEQ - 1);
                    const int h = n >> 6, d = n & 63;
                    *(float2*)(dst + ((size_t)(b * NH + h) * SEQ + s) * DHD + d) = o;
                }
            }
}

__global__ __launch_bounds__(256) void qkv_kernel(
    const float* __restrict__ x,
    const float* __restrict__ Wq, const float* __restrict__ bq,
    const float* __restrict__ Wk, const float* __restrict__ bk,
    const float* __restrict__ Wv, const float* __restrict__ bv)
{
    const float* W; const float* bias; float* dst;
    if (blockIdx.z == 0)      { W = Wq; bias = bq; dst = g_q; }
    else if (blockIdx.z == 1) { W = Wk; bias = bk; dst = g_k; }
    else                      { W = Wv; bias = bv; dst = g_v; }
    gemm_body<0>(x, W, bias, dst);
}

__global__ __launch_bounds__(256) void out_kernel(
    const float* __restrict__ Wh, const float* __restrict__ bhp,
    float* __restrict__ out)
{
    gemm_body<1>(g_att, Wh, bhp, out);
}

// ---------------------------------------------------------------------------
// Fused flash attention (tf32 mma.sync). Block = (b, h, 128-query tile),
// 256 threads, warp w owns rows 16w..16w+15.
// smem: Ps [64k][132] (Q staging, then P tile), Ks [64d][68] (K^T), Vs [64s][68].
// ---------------------------------------------------------------------------
#define PKV 68
#define SM_P (64 * PA)
#define SM_K (64 * PKV)
#define ATTN_SMEM ((SM_P + 2 * SM_K) * 4)

__global__ __launch_bounds__(256) void attn_kernel()
{
    extern __shared__ uint32_t sm[];
    uint32_t (*Ps)[PA]  = (uint32_t(*)[PA]) sm;             // [k=skey][m=qrow]
    uint32_t (*Ks)[PKV] = (uint32_t(*)[PKV])(sm + SM_P);    // [k=d][n=skey]
    uint32_t (*Vs)[PKV] = (uint32_t(*)[PKV])(sm + SM_P + SM_K); // [k=skey][n=d]

    const int tid = threadIdx.x;
    const int w = tid >> 5, t4 = tid & 3, tg = (tid & 31) >> 2;
    const int wm = w * 16;
    const int h = blockIdx.y, b = blockIdx.z;
    const int qbase = blockIdx.x * 128;

    const float* qg  = g_q + ((size_t)(b * NH + h) * SEQ + qbase) * DHD;
    const float* kgb = g_k + ((size_t)(b * NH + h)) * SEQ * DHD;
    const float* vgb = g_v + ((size_t)(b * NH + h)) * SEQ * DHD;

    // Stage Q transposed [d][s] into Ps area, pre-scaled by 1/sqrt(64)
#pragma unroll
    for (int i = 0; i < 8; ++i) {
        int lin = tid + i * 256;                 // 2048 = 128 rows x 16 f4
        int row = lin >> 4, d4 = (lin & 15) << 2;
        float4 v = *(const float4*)(qg + (size_t)row * DHD + d4);
        Ps[d4 + 0][row] = f2tf(v.x * 0.125f);
        Ps[d4 + 1][row] = f2tf(v.y * 0.125f);
        Ps[d4 + 2][row] = f2tf(v.z * 0.125f);
        Ps[d4 + 3][row] = f2tf(v.w * 0.125f);
    }
    __syncthreads();

    // Persistent Q fragments: 8 k-steps x 4 regs
    uint32_t qa[8][4];
#pragma unroll
    for (int ks = 0; ks < 8; ++ks) {
        const int k8 = ks * 8;
        qa[ks][0] = Ps[k8 + t4][wm + tg];
        qa[ks][1] = Ps[k8 + t4][wm + tg + 8];
        qa[ks][2] = Ps[k8 + t4 + 4][wm + tg];
        qa[ks][3] = Ps[k8 + t4 + 4][wm + tg + 8];
    }
    __syncthreads();   // Ps now free for P tiles

    float oc[8][4];
#pragma unroll
    for (int nb = 0; nb < 8; ++nb)
#pragma unroll
        for (int i = 0; i < 4; ++i) oc[nb][i] = 0.f;
    float m0 = -1e30f, m1 = -1e30f, l0 = 0.f, l1 = 0.f;

    for (int kt = 0; kt < SEQ / 64; ++kt) {
        const float* kg = kgb + (size_t)kt * 64 * DHD;
        const float* vg = vgb + (size_t)kt * 64 * DHD;
#pragma unroll
        for (int i = 0; i < 4; ++i) {
            int lin = tid + i * 256;             // 1024 = 64 rows x 16 f4
            int row = lin >> 4, d4 = (lin & 15) << 2;
            float4 v = *(const float4*)(kg + (size_t)row * DHD + d4);
            Ks[d4 + 0][row] = f2tf(v.x); Ks[d4 + 1][row] = f2tf(v.y);
            Ks[d4 + 2][row] = f2tf(v.z); Ks[d4 + 3][row] = f2tf(v.w);
            float4 u = *(const float4*)(vg + (size_t)row * DHD + d4);
            uint4 q; q.x = f2tf(u.x); q.y = f2tf(u.y); q.z = f2tf(u.z); q.w = f2tf(u.w);
            *(uint4*)&Vs[row][d4] = q;
        }
        __syncthreads();

        // S tile: warp's 16 rows x 64 keys
        float sc[8][4];
#pragma unroll
        for (int nb = 0; nb < 8; ++nb)
#pragma unroll
            for (int i = 0; i < 4; ++i) sc[nb][i] = 0.f;
#pragma unroll
        for (int ks = 0; ks < 8; ++ks) {
            const int k8 = ks * 8;
#pragma unroll
            for (int nb = 0; nb < 8; ++nb) {
                uint32_t bf[2];
                bf[0] = Ks[k8 + t4][nb * 8 + tg];
                bf[1] = Ks[k8 + t4 + 4][nb * 8 + tg];
                mma8(sc[nb], qa[ks], bf);
            }
        }

        // Online softmax. Thread holds rows r0 (c0,c1), r1=r0+8 (c2,c3),
        // row spread across lanes t4 (xor 1,2).
        float mx0 = sc[0][0], mx1 = sc[0][2];
#pragma unroll
        for (int nb = 0; nb < 8; ++nb) {
            mx0 = fmaxf(mx0, fmaxf(sc[nb][0], sc[nb][1]));
            mx1 = fmaxf(mx1, fmaxf(sc[nb][2], sc[nb][3]));
        }
        mx0 = fmaxf(mx0, __shfl_xor_sync(~0u, mx0, 1));
        mx0 = fmaxf(mx0, __shfl_xor_sync(~0u, mx0, 2));
        mx1 = fmaxf(mx1, __shfl_xor_sync(~0u, mx1, 1));
        mx1 = fmaxf(mx1, __shfl_xor_sync(~0u, mx1, 2));
        const float nm0 = fmaxf(m0, mx0), nm1 = fmaxf(m1, mx1);
        const float cr0 = __expf(m0 - nm0), cr1 = __expf(m1 - nm1);
        m0 = nm0; m1 = nm1;
        float s0 = 0.f, s1 = 0.f;
#pragma unroll
        for (int nb = 0; nb < 8; ++nb) {
            sc[nb][0] = __expf(sc[nb][0] - m0); s0 += sc[nb][0];
            sc[nb][1] = __expf(sc[nb][1] - m0); s0 += sc[nb][1];
            sc[nb][2] = __expf(sc[nb][2] - m1); s1 += sc[nb][2];
            sc[nb][3] = __expf(sc[nb][3] - m1); s1 += sc[nb][3];
        }
        s0 += __shfl_xor_sync(~0u, s0, 1); s0 += __shfl_xor_sync(~0u, s0, 2);
        s1 += __shfl_xor_sync(~0u, s1, 1); s1 += __shfl_xor_sync(~0u, s1, 2);
        l0 = l0 * cr0 + s0; l1 = l1 * cr1 + s1;
#pragma unroll
        for (int nb = 0; nb < 8; ++nb) {
            oc[nb][0] *= cr0; oc[nb][1] *= cr0;
            oc[nb][2] *= cr1; oc[nb][3] *= cr1;
        }

        // P -> smem in A-operand layout [k=skey][m=qrow] (conflict-free stores)
#pragma unroll
        for (int nb = 0; nb < 8; ++nb) {
            const int col = nb * 8 + 2 * t4;
            Ps[col][wm + tg]         = f2tf(sc[nb][0]);
            Ps[col + 1][wm + tg]     = f2tf(sc[nb][1]);
            Ps[col][wm + tg + 8]     = f2tf(sc[nb][2]);
            Ps[col + 1][wm + tg + 8] = f2tf(sc[nb][3]);
        }
        __syncwarp();   // warp reads only its own 16 P rows

        // O += P @ V
#pragma unroll
        for (int ks = 0; ks < 8; ++ks) {
            const int k8 = ks * 8;
            uint32_t pa[4];
            pa[0] = Ps[k8 + t4][wm + tg];
            pa[1] = Ps[k8 + t4][wm + tg + 8];
            pa[2] = Ps[k8 + t4 + 4][wm + tg];
            pa[3] = Ps[k8 + t4 + 4][wm + tg + 8];
#pragma unroll
            for (int nb = 0; nb < 8; ++nb) {
                uint32_t bf[2];
                bf[0] = Vs[k8 + t4][nb * 8 + tg];
                bf[1] = Vs[k8 + t4 + 4][nb * 8 + tg];
                mma8(oc[nb], pa, bf);
            }
        }
        __syncthreads();   // protect Ks/Vs before next tile load
    }

    const float inv0 = 1.f / l0, inv1 = 1.f / l1;
    float* og = g_att + ((size_t)b * SEQ + qbase + wm + tg) * DIM + h * DHD;
#pragma unroll
    for (int nb = 0; nb < 8; ++nb) {
        const int d = nb * 8 + 2 * t4;
        float2 o0; o0.x = oc[nb][0] * inv0; o0.y = oc[nb][1] * inv0;
        float2 o1; o1.x = oc[nb][2] * inv1; o1.y = oc[nb][3] * inv1;
        *(float2*)(og + d)           = o0;
        *(float2*)(og + 8 * DIM + d) = o1;
    }
}

// ---------------------------------------------------------------------------
extern "C" void kernel_launch(void* const* d_in, const int* in_sizes, int n_in,
                              void* d_out, int out_size)
{
    const float* x  = (const float*)d_in[0];
    const float* Wq = (const float*)d_in[1];
    const float* bq = (const float*)d_in[2];
    const float* Wk = (const float*)d_in[3];
    const float* bk = (const float*)d_in[4];
    const float* Wv = (const float*)d_in[5];
    const float* bv = (const float*)d_in[6];
    const float* Wh = (const float*)d_in[7];
    const float* bh = (const float*)d_in[8];
    float* out = (float*)d_out;

    cudaFuncSetAttribute(attn_kernel,
                         cudaFuncAttributeMaxDynamicSharedMemorySize, ATTN_SMEM);

    // 1. QKV projections (tf32 mma.sync), fused over grid.z
    qkv_kernel<<<dim3(4, 64, 3), 256>>>(x, Wq, bq, Wk, bk, Wv, bv);

    // 2. Fused flash attention
    attn_kernel<<<dim3(SEQ / 128, NH, NB), 256, ATTN_SMEM>>>();

    // 3. Output projection
    out_kernel<<<dim3(4, 64), 256>>>(Wh, bh, out);
}

// round 4
// speedup vs baseline: 6.5259x; 1.0924x over previous
#include <cuda_runtime.h>
#include <cstdint>

#define NB   4
#define SEQ  2048
#define DIM  512
#define NH   8
#define DHD  64
#define PA   136   // pitch ≡ 8 (mod 32): fragment LDS bank = (8*t4+tg)%32, conflict-free
#define PKV  72    // same property for 64-wide K/V tiles

// Scratch (__device__ globals; allocation-free rule)
__device__ float g_q  [(size_t)NB*NH*SEQ*DHD];   // [b,h,s,d] 16 MB (pre-scaled for softmax)
__device__ float g_k  [(size_t)NB*NH*SEQ*DHD];   // [b,h,s,d] 16 MB
__device__ float g_v  [(size_t)NB*NH*SEQ*DHD];   // [b,h,s,d] 16 MB
__device__ float g_att[(size_t)NB*SEQ*DIM];      // [b*s,512] 16 MB

#define QSCALE 0.18033688011112042f   // (1/sqrt(64)) * log2(e)

__device__ __forceinline__ uint32_t f2tf(float x) {
    uint32_t u; asm("cvt.rna.tf32.f32 %0, %1;" : "=r"(u) : "f"(x)); return u;
}

// D += A(m16k8) * B(k8n8), tf32 inputs, f32 accum
__device__ __forceinline__ void mma8(float c[4], const uint32_t a[4], const uint32_t b[2]) {
    asm volatile(
        "mma.sync.aligned.m16n8k8.row.col.f32.tf32.tf32.f32 "
        "{%0,%1,%2,%3}, {%4,%5,%6,%7}, {%8,%9}, {%0,%1,%2,%3};"
        : "+f"(c[0]), "+f"(c[1]), "+f"(c[2]), "+f"(c[3])
        : "r"(a[0]), "r"(a[1]), "r"(a[2]), "r"(a[3]), "r"(b[0]), "r"(b[1]));
}

// ---------------------------------------------------------------------------
// GEMM body: C = A[8192,512] @ W[512,512] + bias. Double-buffered smem +
// register prefetch, one barrier per K-chunk. Block 128x128, 8 warps.
// MODE 0: scatter to [b,h,s,d] (optional scale); MODE 1: plain [m,512]
// ---------------------------------------------------------------------------
template<int MODE>
__device__ __forceinline__ void gemm_body(
    const float* __restrict__ A, const float* __restrict__ W,
    const float* __restrict__ bias, float* __restrict__ dst, float oscale)
{
    extern __shared__ uint32_t sg[];
    uint32_t (*As)[32][PA] = (uint32_t(*)[32][PA])sg;              // [2][k][m]
    uint32_t (*Bs)[32][PA] = (uint32_t(*)[32][PA])(sg + 2*32*PA);  // [2][k][n]

    const int tid = threadIdx.x;
    const int w = tid >> 5, t4 = tid & 3, tg = (tid & 31) >> 2;
    const int wm = (w & 3) * 32, wn = (w >> 2) * 64;
    const int bm = blockIdx.y * 128, bn = blockIdx.x * 128;

    // A staging: lane-along-rows (conflict-free transposed stores)
    const int rowA = (tid & 31) + ((w & 3) << 5);   // 0..127
    const int k40  = w >> 2;                         // k4 = k40 + 2i
    // B staging: coalesced rows
    const int c4b  = (tid & 31) << 2;

    float4 pa[4], pb[4];

#define GEMM_LDG(kc)                                                            \
    {                                                                           \
        _Pragma("unroll")                                                       \
        for (int i = 0; i < 4; ++i)                                             \
            pa[i] = *(const float4*)(A + (size_t)(bm + rowA) * DIM              \
                                     + (kc) * 32 + ((k40 + 2 * i) << 2));       \
        _Pragma("unroll")                                                       \
        for (int i = 0; i < 4; ++i)                                             \
            pb[i] = *(const float4*)(W + (size_t)((kc) * 32 + w + 8 * i) * DIM  \
                                     + bn + c4b);                               \
    }

#define GEMM_STS(bb)                                                            \
    {                                                                           \
        _Pragma("unroll")                                                       \
        for (int i = 0; i < 4; ++i) {                                           \
            const int kq = (k40 + 2 * i) << 2;                                  \
            As[bb][kq + 0][rowA] = f2tf(pa[i].x);                               \
            As[bb][kq + 1][rowA] = f2tf(pa[i].y);                               \
            As[bb][kq + 2][rowA] = f2tf(pa[i].z);                               \
            As[bb][kq + 3][rowA] = f2tf(pa[i].w);                               \
        }                                                                       \
        _Pragma("unroll")                                                       \
        for (int i = 0; i < 4; ++i) {                                           \
            uint4 u;                                                            \
            u.x = f2tf(pb[i].x); u.y = f2tf(pb[i].y);                           \
            u.z = f2tf(pb[i].z); u.w = f2tf(pb[i].w);                           \
            *(uint4*)&Bs[bb][w + 8 * i][c4b] = u;                               \
        }                                                                       \
    }

    float acc[2][8][4];
#pragma unroll
    for (int mb = 0; mb < 2; ++mb)
#pragma unroll
        for (int nb = 0; nb < 8; ++nb)
#pragma unroll
            for (int i = 0; i < 4; ++i) acc[mb][nb][i] = 0.f;

    GEMM_LDG(0);
    GEMM_STS(0);
    __syncthreads();

    for (int kc = 0; kc < 16; ++kc) {
        const int bb = kc & 1;
        if (kc < 15) GEMM_LDG(kc + 1);

#pragma unroll
        for (int ks = 0; ks < 4; ++ks) {
            const int k8 = ks * 8;
            uint32_t a[2][4];
#pragma unroll
            for (int mb = 0; mb < 2; ++mb) {
                const int m0 = wm + mb * 16 + tg;
                a[mb][0] = As[bb][k8 + t4][m0];
                a[mb][1] = As[bb][k8 + t4][m0 + 8];
                a[mb][2] = As[bb][k8 + t4 + 4][m0];
                a[mb][3] = As[bb][k8 + t4 + 4][m0 + 8];
            }
#pragma unroll
            for (int nb = 0; nb < 8; ++nb) {
                uint32_t bf[2];
                const int n0 = wn + nb * 8 + tg;
                bf[0] = Bs[bb][k8 + t4][n0];
                bf[1] = Bs[bb][k8 + t4 + 4][n0];
                mma8(acc[0][nb], a[0], bf);
                mma8(acc[1][nb], a[1], bf);
            }
        }
        if (kc < 15) {
            GEMM_STS(bb ^ 1);
            __syncthreads();
        }
    }

#pragma unroll
    for (int mb = 0; mb < 2; ++mb)
#pragma unroll
        for (int nb = 0; nb < 8; ++nb)
#pragma unroll
            for (int half = 0; half < 2; ++half) {
                const int m = bm + wm + mb * 16 + tg + half * 8;
                const int n = bn + wn + nb * 8 + 2 * t4;
                float2 o;
                o.x = (acc[mb][nb][half * 2 + 0] + bias[n]) * oscale;
                o.y = (acc[mb][nb][half * 2 + 1] + bias[n + 1]) * oscale;
                if (MODE == 1) {
                    *(float2*)(dst + (size_t)m * DIM + n) = o;
                } else {
                    const int b = m >> 11, s = m & (SEQ - 1);
                    const int h = n >> 6, d = n & 63;
                    *(float2*)(dst + ((size_t)(b * NH + h) * SEQ + s) * DHD + d) = o;
                }
            }
}

__global__ __launch_bounds__(256) void qkv_kernel(
    const float* __restrict__ x,
    const float* __restrict__ Wq, const float* __restrict__ bq,
    const float* __restrict__ Wk, const float* __restrict__ bk,
    const float* __restrict__ Wv, const float* __restrict__ bv)
{
    const float* W; const float* bias; float* dst; float sc = 1.f;
    if (blockIdx.z == 0)      { W = Wq; bias = bq; dst = g_q; sc = QSCALE; }
    else if (blockIdx.z == 1) { W = Wk; bias = bk; dst = g_k; }
    else                      { W = Wv; bias = bv; dst = g_v; }
    gemm_body<0>(x, W, bias, dst, sc);
}

__global__ __launch_bounds__(256) void out_kernel(
    const float* __restrict__ Wh, const float* __restrict__ bhp,
    float* __restrict__ out)
{
    gemm_body<1>(g_att, Wh, bhp, out, 1.f);
}

#define GEMM_SMEM (4 * 32 * PA * 4)

// ---------------------------------------------------------------------------
// Fused flash attention. Block = (b, h, 128 queries), 256 threads.
// Q in smem [d][q] (pre-scaled to log2 domain), K/V single-buffer smem with
// register prefetch of the next tile; exp2-domain online softmax.
// ---------------------------------------------------------------------------
#define SM_Q  (64 * PA)
#define SM_P  (64 * PA)
#define SM_KV (64 * PKV)
#define ATTN_SMEM ((SM_Q + SM_P + 2 * SM_KV) * 4)

__global__ __launch_bounds__(256) void attn_kernel()
{
    extern __shared__ uint32_t sm[];
    uint32_t (*Qs)[PA]  = (uint32_t(*)[PA]) sm;                      // [d][q]
    uint32_t (*Ps)[PA]  = (uint32_t(*)[PA])(sm + SM_Q);              // [key][q]
    uint32_t (*Ks)[PKV] = (uint32_t(*)[PKV])(sm + SM_Q + SM_P);      // [d][key]
    uint32_t (*Vs)[PKV] = (uint32_t(*)[PKV])(sm + SM_Q + SM_P + SM_KV); // [key][d]

    const int tid = threadIdx.x;
    const int w = tid >> 5, l = tid & 31, t4 = tid & 3, tg = l >> 2;
    const int wm = w * 16;
    const int h = blockIdx.y, b = blockIdx.z;
    const int qbase = blockIdx.x * 128;

    const float* qg  = g_q + ((size_t)(b * NH + h) * SEQ + qbase) * DHD;
    const float* kgb = g_k + ((size_t)(b * NH + h)) * SEQ * DHD;
    const float* vgb = g_v + ((size_t)(b * NH + h)) * SEQ * DHD;

    // ---- stage Q (transposed, conflict-free stores: lanes along rows) ----
#pragma unroll
    for (int i = 0; i < 8; ++i) {
        const int row = l + ((i & 3) << 5);          // 0..127 (q)
        const int d4q = 2 * w + (i >> 2);            // 0..15
        float4 v = *(const float4*)(qg + (size_t)row * DHD + (d4q << 2));
        const int kq = d4q << 2;
        Qs[kq + 0][row] = f2tf(v.x); Qs[kq + 1][row] = f2tf(v.y);
        Qs[kq + 2][row] = f2tf(v.z); Qs[kq + 3][row] = f2tf(v.w);
    }

    // K tile staging: lanes along key-rows (conflict-free transposed stores)
    float4 pk[4], pv[4];
#define ATTN_LDG(kt)                                                            \
    {                                                                           \
        const float* kg = kgb + (size_t)(kt) * 64 * DHD;                        \
        const float* vg = vgb + (size_t)(kt) * 64 * DHD;                        \
        _Pragma("unroll")                                                       \
        for (int i = 0; i < 4; ++i) {                                           \
            const int row = l + ((i & 1) << 5);                                 \
            const int d4q = 2 * w + (i >> 1);                                   \
            pk[i] = *(const float4*)(kg + (size_t)row * DHD + (d4q << 2));      \
        }                                                                       \
        _Pragma("unroll")                                                       \
        for (int i = 0; i < 4; ++i) {                                           \
            const int row = 2 * (w + 8 * i) + (l >> 4);                         \
            pv[i] = *(const float4*)(vg + (size_t)row * DHD + ((l & 15) << 2)); \
        }                                                                       \
    }

#define ATTN_STS()                                                              \
    {                                                                           \
        _Pragma("unroll")                                                       \
        for (int i = 0; i < 4; ++i) {                                           \
            const int row = l + ((i & 1) << 5);                                 \
            const int kq = (2 * w + (i >> 1)) << 2;                             \
            Ks[kq + 0][row] = f2tf(pk[i].x); Ks[kq + 1][row] = f2tf(pk[i].y);   \
            Ks[kq + 2][row] = f2tf(pk[i].z); Ks[kq + 3][row] = f2tf(pk[i].w);   \
        }                                                                       \
        _Pragma("unroll")                                                       \
        for (int i = 0; i < 4; ++i) {                                           \
            const int row = 2 * (w + 8 * i) + (l >> 4);                         \
            uint4 u;                                                            \
            u.x = f2tf(pv[i].x); u.y = f2tf(pv[i].y);                           \
            u.z = f2tf(pv[i].z); u.w = f2tf(pv[i].w);                           \
            *(uint4*)&Vs[row][(l & 15) << 2] = u;                               \
        }                                                                       \
    }

    ATTN_LDG(0);
    ATTN_STS();
    __syncthreads();   // Q + tile 0 ready

    float oc[8][4];
#pragma unroll
    for (int nb = 0; nb < 8; ++nb)
#pragma unroll
        for (int i = 0; i < 4; ++i) oc[nb][i] = 0.f;
    float m0 = -1e30f, m1 = -1e30f, l0 = 0.f, l1 = 0.f;

    for (int kt = 0; kt < SEQ / 64; ++kt) {
        if (kt < SEQ / 64 - 1) ATTN_LDG(kt + 1);   // hide LDG under S+softmax+PV

        // ---- S = Q K^T (log2 domain; Q pre-scaled) ----
        float sc[8][4];
#pragma unroll
        for (int nb = 0; nb < 8; ++nb)
#pragma unroll
            for (int i = 0; i < 4; ++i) sc[nb][i] = 0.f;
#pragma unroll
        for (int ks = 0; ks < 8; ++ks) {
            const int k8 = ks * 8;
            uint32_t qa[4];
            qa[0] = Qs[k8 + t4][wm + tg];
            qa[1] = Qs[k8 + t4][wm + tg + 8];
            qa[2] = Qs[k8 + t4 + 4][wm + tg];
            qa[3] = Qs[k8 + t4 + 4][wm + tg + 8];
#pragma unroll
            for (int nb = 0; nb < 8; ++nb) {
                uint32_t bf[2];
                bf[0] = Ks[k8 + t4][nb * 8 + tg];
                bf[1] = Ks[k8 + t4 + 4][nb * 8 + tg];
                mma8(sc[nb], qa, bf);
            }
        }

        // ---- online softmax (exp2 domain) ----
        float mx0 = sc[0][0], mx1 = sc[0][2];
#pragma unroll
        for (int nb = 0; nb < 8; ++nb) {
            mx0 = fmaxf(mx0, fmaxf(sc[nb][0], sc[nb][1]));
            mx1 = fmaxf(mx1, fmaxf(sc[nb][2], sc[nb][3]));
        }
        mx0 = fmaxf(mx0, __shfl_xor_sync(~0u, mx0, 1));
        mx0 = fmaxf(mx0, __shfl_xor_sync(~0u, mx0, 2));
        mx1 = fmaxf(mx1, __shfl_xor_sync(~0u, mx1, 1));
        mx1 = fmaxf(mx1, __shfl_xor_sync(~0u, mx1, 2));
        const float nm0 = fmaxf(m0, mx0), nm1 = fmaxf(m1, mx1);
        const float cr0 = exp2f(m0 - nm0), cr1 = exp2f(m1 - nm1);
        m0 = nm0; m1 = nm1;
        float s0 = 0.f, s1 = 0.f;
#pragma unroll
        for (int nb = 0; nb < 8; ++nb) {
            sc[nb][0] = exp2f(sc[nb][0] - m0); s0 += sc[nb][0];
            sc[nb][1] = exp2f(sc[nb][1] - m0); s0 += sc[nb][1];
            sc[nb][2] = exp2f(sc[nb][2] - m1); s1 += sc[nb][2];
            sc[nb][3] = exp2f(sc[nb][3] - m1); s1 += sc[nb][3];
        }
        s0 += __shfl_xor_sync(~0u, s0, 1); s0 += __shfl_xor_sync(~0u, s0, 2);
        s1 += __shfl_xor_sync(~0u, s1, 1); s1 += __shfl_xor_sync(~0u, s1, 2);
        l0 = l0 * cr0 + s0; l1 = l1 * cr1 + s1;
#pragma unroll
        for (int nb = 0; nb < 8; ++nb) {
            oc[nb][0] *= cr0; oc[nb][1] *= cr0;
            oc[nb][2] *= cr1; oc[nb][3] *= cr1;
        }

        // ---- P -> smem (warp-local columns) ----
#pragma unroll
        for (int nb = 0; nb < 8; ++nb) {
            const int col = nb * 8 + 2 * t4;
            Ps[col][wm + tg]         = f2tf(sc[nb][0]);
            Ps[col + 1][wm + tg]     = f2tf(sc[nb][1]);
            Ps[col][wm + tg + 8]     = f2tf(sc[nb][2]);
            Ps[col + 1][wm + tg + 8] = f2tf(sc[nb][3]);
        }
        __syncwarp();

        // ---- O += P V ----
#pragma unroll
        for (int ks = 0; ks < 8; ++ks) {
            const int k8 = ks * 8;
            uint32_t pa[4];
            pa[0] = Ps[k8 + t4][wm + tg];
            pa[1] = Ps[k8 + t4][wm + tg + 8];
            pa[2] = Ps[k8 + t4 + 4][wm + tg];
            pa[3] = Ps[k8 + t4 + 4][wm + tg + 8];
#pragma unroll
            for (int nb = 0; nb < 8; ++nb) {
                uint32_t bf[2];
                bf[0] = Vs[k8 + t4][nb * 8 + tg];
                bf[1] = Vs[k8 + t4 + 4][nb * 8 + tg];
                mma8(oc[nb], pa, bf);
            }
        }
        __syncthreads();           // everyone done reading Ks/Vs
        if (kt < SEQ / 64 - 1) {
            ATTN_STS();            // write tile kt+1
            __syncthreads();
        }
    }

    const float inv0 = 1.f / l0, inv1 = 1.f / l1;
    float* og = g_att + ((size_t)b * SEQ + qbase + wm + tg) * DIM + h * DHD;
#pragma unroll
    for (int nb = 0; nb < 8; ++nb) {
        const int d = nb * 8 + 2 * t4;
        float2 o0; o0.x = oc[nb][0] * inv0; o0.y = oc[nb][1] * inv0;
        float2 o1; o1.x = oc[nb][2] * inv1; o1.y = oc[nb][3] * inv1;
        *(float2*)(og + d)           = o0;
        *(float2*)(og + 8 * DIM + d) = o1;
    }
}

// ---------------------------------------------------------------------------
extern "C" void kernel_launch(void* const* d_in, const int* in_sizes, int n_in,
                              void* d_out, int out_size)
{
    const float* x  = (const float*)d_in[0];
    const float* Wq = (const float*)d_in[1];
    const float* bq = (const float*)d_in[2];
    const float* Wk = (const float*)d_in[3];
    const float* bk = (const float*)d_in[4];
    const float* Wv = (const float*)d_in[5];
    const float* bv = (const float*)d_in[6];
    const float* Wh = (const float*)d_in[7];
    const float* bh = (const float*)d_in[8];
    float* out = (float*)d_out;

    cudaFuncSetAttribute(qkv_kernel, cudaFuncAttributeMaxDynamicSharedMemorySize, GEMM_SMEM);
    cudaFuncSetAttribute(out_kernel, cudaFuncAttributeMaxDynamicSharedMemorySize, GEMM_SMEM);
    cudaFuncSetAttribute(attn_kernel, cudaFuncAttributeMaxDynamicSharedMemorySize, ATTN_SMEM);

    // 1. QKV projections (Q pre-scaled into log2-softmax domain)
    qkv_kernel<<<dim3(4, 64, 3), 256, GEMM_SMEM>>>(x, Wq, bq, Wk, bk, Wv, bv);

    // 2. Fused flash attention
    attn_kernel<<<dim3(SEQ / 128, NH, NB), 256, ATTN_SMEM>>>();

    // 3. Output projection
    out_kernel<<<dim3(4, 64), 256, GEMM_SMEM>>>(Wh, bh, out);
}

// round 5
// speedup vs baseline: 7.9148x; 1.2128x over previous
#include <cuda_runtime.h>
#include <cstdint>

#define NB   4
#define SEQ  2048
#define DIM  512
#define NH   8
#define DHD  64
#define QSCALE 0.18033688011112042f   // (1/sqrt(64)) * log2(e)

// Scratch (__device__ globals; allocation-free rule). All values tf32-rounded.
__device__ float g_x  [(size_t)NB*SEQ*DIM];      // rounded copy of x
__device__ float g_w  [4ull*DIM*DIM];            // rounded Wq,Wk,Wv,Wh
__device__ float g_qT [(size_t)NB*NH*DHD*SEQ];   // [b,h,d,s], pre-scaled log2 domain
__device__ float g_kT [(size_t)NB*NH*DHD*SEQ];   // [b,h,d,s]
__device__ float g_v  [(size_t)NB*NH*SEQ*DHD];   // [b,h,s,d]
__device__ float g_att[(size_t)NB*SEQ*DIM];      // [b*s,512]

__device__ __forceinline__ uint32_t f2tf(float x) {
    uint32_t u; asm("cvt.rna.tf32.f32 %0, %1;" : "=r"(u) : "f"(x)); return u;
}
__device__ __forceinline__ float rnd(float x) { return __uint_as_float(f2tf(x)); }

__device__ __forceinline__ void mma8(float c[4], const uint32_t a[4], const uint32_t b[2]) {
    asm volatile(
        "mma.sync.aligned.m16n8k8.row.col.f32.tf32.tf32.f32 "
        "{%0,%1,%2,%3}, {%4,%5,%6,%7}, {%8,%9}, {%0,%1,%2,%3};"
        : "+f"(c[0]), "+f"(c[1]), "+f"(c[2]), "+f"(c[3])
        : "r"(a[0]), "r"(a[1]), "r"(a[2]), "r"(a[3]), "r"(b[0]), "r"(b[1]));
}

__device__ __forceinline__ uint32_t smem_u32(const void* p) {
    uint32_t a;
    asm("{ .reg .u64 t; cvta.to.shared.u64 t, %1; cvt.u32.u64 %0, t; }" : "=r"(a) : "l"(p));
    return a;
}
__device__ __forceinline__ void cpa(uint32_t dst, const void* src) {
    asm volatile("cp.async.cg.shared.global [%0], [%1], 16;" :: "r"(dst), "l"(src));
}
#define CP_COMMIT() asm volatile("cp.async.commit_group;" ::: "memory")
#define CP_WAIT(n)  asm volatile("cp.async.wait_group %0;" :: "n"(n) : "memory")

// ---------------------------------------------------------------------------
// Prep: tf32-round x and the four weight matrices into scratch.
// ---------------------------------------------------------------------------
#define XF4  ((NB*SEQ*DIM)/4)          // 1,048,576 float4
#define WF4  ((DIM*DIM)/4)             // 65,536 float4 per matrix
__global__ __launch_bounds__(256) void prep_kernel(
    const float* __restrict__ x,  const float* __restrict__ Wq,
    const float* __restrict__ Wk, const float* __restrict__ Wv,
    const float* __restrict__ Wh)
{
    const int idx = blockIdx.x * 256 + threadIdx.x;
    const float4* src; float4* dst;
    if (idx < XF4) { src = (const float4*)x + idx; dst = (float4*)g_x + idx; }
    else {
        int r = idx - XF4, wsel = r >> 16, off = r & (WF4 - 1);
        const float* Ws = (wsel == 0) ? Wq : (wsel == 1) ? Wk : (wsel == 2) ? Wv : Wh;
        src = (const float4*)Ws + off;
        dst = (float4*)(g_w + (size_t)wsel * DIM * DIM) + off;
    }
    float4 v = *src;
    v.x = rnd(v.x); v.y = rnd(v.y); v.z = rnd(v.z); v.w = rnd(v.w);
    *dst = v;
}

// ---------------------------------------------------------------------------
// GEMM: C = A[8192,512] @ W[512,512] + bias. cp.async double-buffered.
// Block 128x128, 8 warps. As [m][k] pitch 36, Bs [k][n] pitch 136 (both
// conflict-free for fragment LDS and 16B-aligned rows).
// mode: 0 Q->g_qT (scaled), 1 K->g_kT, 2 V->g_v, 3 plain out (no rounding)
// ---------------------------------------------------------------------------
#define PAK 36
#define PBN 136
#define ASF (128*PAK)       // 4608 floats per A buffer
#define BSF (32*PBN)        // 4352 floats per B buffer
#define GEMM_SMEM ((2*ASF + 2*BSF) * 4)

__device__ __forceinline__ void gemm_body(
    const float* __restrict__ A, const float* __restrict__ W,
    const float* __restrict__ bias, float* __restrict__ dst,
    float oscale, int mode)
{
    extern __shared__ float sg[];
    float* Asf[2] = { sg, sg + ASF };
    float* Bsf[2] = { sg + 2*ASF, sg + 2*ASF + BSF };
    uint32_t asb[2] = { smem_u32(Asf[0]), smem_u32(Asf[1]) };
    uint32_t bsb[2] = { smem_u32(Bsf[0]), smem_u32(Bsf[1]) };

    const int tid = threadIdx.x;
    const int w = tid >> 5, t4 = tid & 3, tg = (tid & 31) >> 2;
    const int wm = (w & 3) * 32, wn = (w >> 2) * 64;
    const int bm = blockIdx.y * 128, bn = blockIdx.x * 128;

    // cp.async chunk coords
    int amr[4], af4[4], bkr[4], bf4[4];
#pragma unroll
    for (int i = 0; i < 4; ++i) {
        const int c = tid + i * 256;
        amr[i] = c >> 3;  af4[i] = (c & 7) << 2;    // A: 128 rows x 8 f4
        bkr[i] = c >> 5;  bf4[i] = (c & 31) << 2;   // B: 32 rows x 32 f4
    }

#define G_ISSUE(kc, bb)                                                         \
    {                                                                           \
        _Pragma("unroll")                                                       \
        for (int i = 0; i < 4; ++i)                                             \
            cpa(asb[bb] + (amr[i] * PAK + af4[i]) * 4,                          \
                A + (size_t)(bm + amr[i]) * DIM + (kc) * 32 + af4[i]);          \
        _Pragma("unroll")                                                       \
        for (int i = 0; i < 4; ++i)                                             \
            cpa(bsb[bb] + (bkr[i] * PBN + bf4[i]) * 4,                          \
                W + (size_t)((kc) * 32 + bkr[i]) * DIM + bn + bf4[i]);          \
        CP_COMMIT();                                                            \
    }

    float acc[2][8][4];
#pragma unroll
    for (int mb = 0; mb < 2; ++mb)
#pragma unroll
        for (int nb = 0; nb < 8; ++nb)
#pragma unroll
            for (int i = 0; i < 4; ++i) acc[mb][nb][i] = 0.f;

    G_ISSUE(0, 0);
    for (int kc = 0; kc < 16; ++kc) {
        const int bb = kc & 1;
        if (kc < 15) G_ISSUE(kc + 1, bb ^ 1);
        if (kc < 15) { CP_WAIT(1); } else { CP_WAIT(0); }
        __syncthreads();

        const uint32_t* As = (const uint32_t*)Asf[bb];
        const uint32_t* Bs = (const uint32_t*)Bsf[bb];
#pragma unroll
        for (int ks = 0; ks < 4; ++ks) {
            const int k8 = ks * 8;
            uint32_t a[2][4];
#pragma unroll
            for (int mb = 0; mb < 2; ++mb) {
                const int m0 = wm + mb * 16 + tg;
                a[mb][0] = As[m0 * PAK + k8 + t4];
                a[mb][1] = As[(m0 + 8) * PAK + k8 + t4];
                a[mb][2] = As[m0 * PAK + k8 + t4 + 4];
                a[mb][3] = As[(m0 + 8) * PAK + k8 + t4 + 4];
            }
#pragma unroll
            for (int nb = 0; nb < 8; ++nb) {
                uint32_t bf[2];
                const int n0 = wn + nb * 8 + tg;
                bf[0] = Bs[(k8 + t4) * PBN + n0];
                bf[1] = Bs[(k8 + t4 + 4) * PBN + n0];
                mma8(acc[0][nb], a[0], bf);
                mma8(acc[1][nb], a[1], bf);
            }
        }
        __syncthreads();   // release buffer bb for reuse at kc+2
    }

#pragma unroll
    for (int mb = 0; mb < 2; ++mb)
#pragma unroll
        for (int nb = 0; nb < 8; ++nb)
#pragma unroll
            for (int half = 0; half < 2; ++half) {
                const int m = bm + wm + mb * 16 + tg + half * 8;
                const int n = bn + wn + nb * 8 + 2 * t4;
                float vx = (acc[mb][nb][half * 2 + 0] + bias[n]) * oscale;
                float vy = (acc[mb][nb][half * 2 + 1] + bias[n + 1]) * oscale;
                if (mode == 3) {
                    float2 o; o.x = vx; o.y = vy;
                    *(float2*)(dst + (size_t)m * DIM + n) = o;
                } else {
                    const int b = m >> 11, s = m & (SEQ - 1);
                    const int h = n >> 6, d = n & 63;
                    if (mode == 2) {
                        float2 o; o.x = rnd(vx); o.y = rnd(vy);
                        *(float2*)(dst + ((size_t)(b * NH + h) * SEQ + s) * DHD + d) = o;
                    } else {
                        float* base = dst + ((size_t)(b * NH + h) * DHD + d) * SEQ + s;
                        base[0]   = rnd(vx);
                        base[SEQ] = rnd(vy);
                    }
                }
            }
}

__global__ __launch_bounds__(256, 2) void qkv_kernel(
    const float* __restrict__ bq, const float* __restrict__ bk,
    const float* __restrict__ bv)
{
    const int z = blockIdx.z;
    const float* W = g_w + (size_t)z * DIM * DIM;
    const float* bias; float* dst; float sc = 1.f;
    if (z == 0)      { bias = bq; dst = g_qT; sc = QSCALE; }
    else if (z == 1) { bias = bk; dst = g_kT; }
    else             { bias = bv; dst = g_v; }
    gemm_body(g_x, W, bias, dst, sc, z);
}

__global__ __launch_bounds__(256, 2) void out_kernel(
    const float* __restrict__ bhp, float* __restrict__ out)
{
    gemm_body(g_att, g_w + 3ull * DIM * DIM, bhp, out, 1.f, 3);
}

// ---------------------------------------------------------------------------
// Fused flash attention. Block = (b, h, 128 queries), 256 threads, 2 CTA/SM.
// Q fragments persistent in regs (staged via Ps smem). K/V double-buffered
// cp.async tiles: Ks [d][key] pitch 72 (direct rows of g_kT), Vs [key][d].
// ---------------------------------------------------------------------------
#define PKV  72
#define PSF  (64*136)     // 8704 floats (Q staging, then P tile)
#define KVF  (64*PKV)     // 4608 floats per tile buffer
#define ATTN_SMEM ((PSF + 4*KVF) * 4)

__global__ __launch_bounds__(256, 2) void attn_kernel()
{
    extern __shared__ float sa[];
    float* Psf = sa;
    float* Ksf[2] = { sa + PSF, sa + PSF + KVF };
    float* Vsf[2] = { sa + PSF + 2*KVF, sa + PSF + 3*KVF };
    const uint32_t psb = smem_u32(Psf);
    uint32_t ksb[2] = { smem_u32(Ksf[0]), smem_u32(Ksf[1]) };
    uint32_t vsb[2] = { smem_u32(Vsf[0]), smem_u32(Vsf[1]) };

    const int tid = threadIdx.x;
    const int w = tid >> 5, t4 = tid & 3, tg = (tid & 31) >> 2;
    const int wm = w * 16;
    const int h = blockIdx.y, b = blockIdx.z;
    const int qbase = blockIdx.x * 128;

    const float* qT = g_qT + (size_t)(b * NH + h) * DHD * SEQ;   // [d][s]
    const float* kT = g_kT + (size_t)(b * NH + h) * DHD * SEQ;   // [d][s]
    const float* vg = g_v  + (size_t)(b * NH + h) * SEQ * DHD;   // [s][d]

    // chunk coords: K/V tiles 64 rows x 16 f4; Q tile 64 rows x 32 f4
    int kvr[4], kvf[4], qr[8], qf[8];
#pragma unroll
    for (int i = 0; i < 4; ++i) {
        const int c = tid + i * 256;
        kvr[i] = c >> 4; kvf[i] = (c & 15) << 2;
    }
#pragma unroll
    for (int i = 0; i < 8; ++i) {
        const int c = tid + i * 256;
        qr[i] = c >> 5; qf[i] = (c & 31) << 2;
    }

#define A_ISSUE(kt, bb)                                                          \
    {                                                                            \
        _Pragma("unroll")                                                        \
        for (int i = 0; i < 4; ++i)                                              \
            cpa(ksb[bb] + (kvr[i] * PKV + kvf[i]) * 4,                           \
                kT + (size_t)kvr[i] * SEQ + (kt) * 64 + kvf[i]);                 \
        _Pragma("unroll")                                                        \
        for (int i = 0; i < 4; ++i)                                              \
            cpa(vsb[bb] + (kvr[i] * PKV + kvf[i]) * 4,                           \
                vg + (size_t)((kt) * 64 + kvr[i]) * DHD + kvf[i]);               \
        CP_COMMIT();                                                             \
    }

    // Stage Q into Ps, then pull persistent fragments
#pragma unroll
    for (int i = 0; i < 8; ++i)
        cpa(psb + (qr[i] * 136 + qf[i]) * 4,
            qT + (size_t)qr[i] * SEQ + qbase + qf[i]);
    CP_COMMIT();
    A_ISSUE(0, 0);
    CP_WAIT(1);          // Q group done
    __syncthreads();

    uint32_t qa[8][4];
    {
        const uint32_t* Ps = (const uint32_t*)Psf;
#pragma unroll
        for (int ks = 0; ks < 8; ++ks) {
            const int k8 = ks * 8;
            qa[ks][0] = Ps[(k8 + t4) * 136 + wm + tg];
            qa[ks][1] = Ps[(k8 + t4) * 136 + wm + tg + 8];
            qa[ks][2] = Ps[(k8 + t4 + 4) * 136 + wm + tg];
            qa[ks][3] = Ps[(k8 + t4 + 4) * 136 + wm + tg + 8];
        }
    }
    __syncthreads();   // Ps free for P tiles

    float oc[8][4];
#pragma unroll
    for (int nb = 0; nb < 8; ++nb)
#pragma unroll
        for (int i = 0; i < 4; ++i) oc[nb][i] = 0.f;
    float m0 = -1e30f, m1 = -1e30f, l0 = 0.f, l1 = 0.f;

    for (int kt = 0; kt < SEQ / 64; ++kt) {
        const int bb = kt & 1;
        if (kt < SEQ / 64 - 1) A_ISSUE(kt + 1, bb ^ 1);
        if (kt < SEQ / 64 - 1) { CP_WAIT(1); } else { CP_WAIT(0); }
        __syncthreads();   // tile kt ready

        const uint32_t* Ks = (const uint32_t*)Ksf[bb];
        const uint32_t* Vs = (const uint32_t*)Vsf[bb];
        uint32_t* Ps = (uint32_t*)Psf;

        // ---- S = Q K^T (log2 domain) ----
        float sc[8][4];
#pragma unroll
        for (int nb = 0; nb < 8; ++nb)
#pragma unroll
            for (int i = 0; i < 4; ++i) sc[nb][i] = 0.f;
#pragma unroll
        for (int ks = 0; ks < 8; ++ks) {
            const int k8 = ks * 8;
#pragma unroll
            for (int nb = 0; nb < 8; ++nb) {
                uint32_t bf[2];
                bf[0] = Ks[(k8 + t4) * PKV + nb * 8 + tg];
                bf[1] = Ks[(k8 + t4 + 4) * PKV + nb * 8 + tg];
                mma8(sc[nb], qa[ks], bf);
            }
        }

        // ---- online softmax (exp2 domain) ----
        float mx0 = sc[0][0], mx1 = sc[0][2];
#pragma unroll
        for (int nb = 0; nb < 8; ++nb) {
            mx0 = fmaxf(mx0, fmaxf(sc[nb][0], sc[nb][1]));
            mx1 = fmaxf(mx1, fmaxf(sc[nb][2], sc[nb][3]));
        }
        mx0 = fmaxf(mx0, __shfl_xor_sync(~0u, mx0, 1));
        mx0 = fmaxf(mx0, __shfl_xor_sync(~0u, mx0, 2));
        mx1 = fmaxf(mx1, __shfl_xor_sync(~0u, mx1, 1));
        mx1 = fmaxf(mx1, __shfl_xor_sync(~0u, mx1, 2));
        const float nm0 = fmaxf(m0, mx0), nm1 = fmaxf(m1, mx1);
        const float cr0 = exp2f(m0 - nm0), cr1 = exp2f(m1 - nm1);
        m0 = nm0; m1 = nm1;
        float s0 = 0.f, s1 = 0.f;
#pragma unroll
        for (int nb = 0; nb < 8; ++nb) {
            sc[nb][0] = exp2f(sc[nb][0] - m0); s0 += sc[nb][0];
            sc[nb][1] = exp2f(sc[nb][1] - m0); s0 += sc[nb][1];
            sc[nb][2] = exp2f(sc[nb][2] - m1); s1 += sc[nb][2];
            sc[nb][3] = exp2f(sc[nb][3] - m1); s1 += sc[nb][3];
        }
        s0 += __shfl_xor_sync(~0u, s0, 1); s0 += __shfl_xor_sync(~0u, s0, 2);
        s1 += __shfl_xor_sync(~0u, s1, 1); s1 += __shfl_xor_sync(~0u, s1, 2);
        l0 = l0 * cr0 + s0; l1 = l1 * cr1 + s1;
#pragma unroll
        for (int nb = 0; nb < 8; ++nb) {
            oc[nb][0] *= cr0; oc[nb][1] *= cr0;
            oc[nb][2] *= cr1; oc[nb][3] *= cr1;
        }

        // ---- P -> smem (warp-local columns) ----
#pragma unroll
        for (int nb = 0; nb < 8; ++nb) {
            const int col = nb * 8 + 2 * t4;
            Ps[col * 136 + wm + tg]           = f2tf(sc[nb][0]);
            Ps[(col + 1) * 136 + wm + tg]     = f2tf(sc[nb][1]);
            Ps[col * 136 + wm + tg + 8]       = f2tf(sc[nb][2]);
            Ps[(col + 1) * 136 + wm + tg + 8] = f2tf(sc[nb][3]);
        }
        __syncwarp();

        // ---- O += P V ----
#pragma unroll
        for (int ks = 0; ks < 8; ++ks) {
            const int k8 = ks * 8;
            uint32_t pa[4];
            pa[0] = Ps[(k8 + t4) * 136 + wm + tg];
            pa[1] = Ps[(k8 + t4) * 136 + wm + tg + 8];
            pa[2] = Ps[(k8 + t4 + 4) * 136 + wm + tg];
            pa[3] = Ps[(k8 + t4 + 4) * 136 + wm + tg + 8];
#pragma unroll
            for (int nb = 0; nb < 8; ++nb) {
                uint32_t bf[2];
                bf[0] = Vs[(k8 + t4) * PKV + nb * 8 + tg];
                bf[1] = Vs[(k8 + t4 + 4) * PKV + nb * 8 + tg];
                mma8(oc[nb], pa, bf);
            }
        }
        __syncthreads();   // release buffer bb for issue at kt+1
    }

    const float inv0 = 1.f / l0, inv1 = 1.f / l1;
    float* og = g_att + ((size_t)b * SEQ + qbase + wm + tg) * DIM + h * DHD;
#pragma unroll
    for (int nb = 0; nb < 8; ++nb) {
        const int d = nb * 8 + 2 * t4;
        float2 o0; o0.x = rnd(oc[nb][0] * inv0); o0.y = rnd(oc[nb][1] * inv0);
        float2 o1; o1.x = rnd(oc[nb][2] * inv1); o1.y = rnd(oc[nb][3] * inv1);
        *(float2*)(og + d)           = o0;
        *(float2*)(og + 8 * DIM + d) = o1;
    }
}

// ---------------------------------------------------------------------------
extern "C" void kernel_launch(void* const* d_in, const int* in_sizes, int n_in,
                              void* d_out, int out_size)
{
    const float* x  = (const float*)d_in[0];
    const float* Wq = (const float*)d_in[1];
    const float* bq = (const float*)d_in[2];
    const float* Wk = (const float*)d_in[3];
    const float* bk = (const float*)d_in[4];
    const float* Wv = (const float*)d_in[5];
    const float* bv = (const float*)d_in[6];
    const float* Wh = (const float*)d_in[7];
    const float* bh = (const float*)d_in[8];
    float* out = (float*)d_out;

    cudaFuncSetAttribute(qkv_kernel, cudaFuncAttributeMaxDynamicSharedMemorySize, GEMM_SMEM);
    cudaFuncSetAttribute(out_kernel, cudaFuncAttributeMaxDynamicSharedMemorySize, GEMM_SMEM);
    cudaFuncSetAttribute(attn_kernel, cudaFuncAttributeMaxDynamicSharedMemorySize, ATTN_SMEM);

    // 0. tf32-round inputs + weights
    prep_kernel<<<(XF4 + 4 * WF4 + 255) / 256, 256>>>(x, Wq, Wk, Wv, Wh);

    // 1. QKV projections (Q pre-scaled into log2 domain; Q/K stored [b,h,d,s])
    qkv_kernel<<<dim3(4, 64, 3), 256, GEMM_SMEM>>>(bq, bk, bv);

    // 2. Fused flash attention
    attn_kernel<<<dim3(SEQ / 128, NH, NB), 256, ATTN_SMEM>>>();

    // 3. Output projection
    out_kernel<<<dim3(4, 64), 256, GEMM_SMEM>>>(bh, out);
}

// round 7
// speedup vs baseline: 9.5910x; 1.2118x over previous
#include <cuda_runtime.h>
#include <cstdint>

#define NB   4
#define SEQ  2048
#define DIM  512
#define NH   8
#define DHD  64
#define QSCALE 0.18033688011112042f   // (1/sqrt(64)) * log2(e)

// Scratch (__device__ globals; allocation-free rule). All values tf32-rounded.
__device__ float g_x  [(size_t)NB*SEQ*DIM];      // rounded copy of x
__device__ float g_w  [4ull*DIM*DIM];            // rounded Wq,Wk,Wv,Wh
__device__ float g_qT [(size_t)NB*NH*DHD*SEQ];   // [b,h,d,s], pre-scaled log2 domain
__device__ float g_kT [(size_t)NB*NH*DHD*SEQ];   // [b,h,d,s]
__device__ float g_v  [(size_t)NB*NH*SEQ*DHD];   // [b,h,s,d]
__device__ float g_att[(size_t)NB*SEQ*DIM];      // [b*s,512]

__device__ __forceinline__ uint32_t f2tf(float x) {
    uint32_t u; asm("cvt.rna.tf32.f32 %0, %1;" : "=r"(u) : "f"(x)); return u;
}
__device__ __forceinline__ float rnd(float x) { return __uint_as_float(f2tf(x)); }
__device__ __forceinline__ float ex2(float x) {
    float y; asm("ex2.approx.ftz.f32 %0, %1;" : "=f"(y) : "f"(x)); return y;
}

__device__ __forceinline__ void mma8(float c[4], const uint32_t a[4], const uint32_t b[2]) {
    asm volatile(
        "mma.sync.aligned.m16n8k8.row.col.f32.tf32.tf32.f32 "
        "{%0,%1,%2,%3}, {%4,%5,%6,%7}, {%8,%9}, {%0,%1,%2,%3};"
        : "+f"(c[0]), "+f"(c[1]), "+f"(c[2]), "+f"(c[3])
        : "r"(a[0]), "r"(a[1]), "r"(a[2]), "r"(a[3]), "r"(b[0]), "r"(b[1]));
}

__device__ __forceinline__ uint32_t smem_u32(const void* p) {
    uint32_t a;
    asm("{ .reg .u64 t; cvta.to.shared.u64 t, %1; cvt.u32.u64 %0, t; }" : "=r"(a) : "l"(p));
    return a;
}
__device__ __forceinline__ void cpa(uint32_t dst, const void* src) {
    asm volatile("cp.async.cg.shared.global [%0], [%1], 16;" :: "r"(dst), "l"(src));
}
#define CP_COMMIT() asm volatile("cp.async.commit_group;" ::: "memory")
#define CP_WAIT(n)  asm volatile("cp.async.wait_group %0;" :: "n"(n) : "memory")

// ---------------------------------------------------------------------------
// Prep: tf32-round x and the four weight matrices into scratch.
// ---------------------------------------------------------------------------
#define XF4  ((NB*SEQ*DIM)/4)
#define WF4  ((DIM*DIM)/4)
__global__ __launch_bounds__(256) void prep_kernel(
    const float* __restrict__ x,  const float* __restrict__ Wq,
    const float* __restrict__ Wk, const float* __restrict__ Wv,
    const float* __restrict__ Wh)
{
    const int idx = blockIdx.x * 256 + threadIdx.x;
    const float4* src; float4* dst;
    if (idx < XF4) { src = (const float4*)x + idx; dst = (float4*)g_x + idx; }
    else {
        int r = idx - XF4, wsel = r >> 16, off = r & (WF4 - 1);
        const float* Ws = (wsel == 0) ? Wq : (wsel == 1) ? Wk : (wsel == 2) ? Wv : Wh;
        src = (const float4*)Ws + off;
        dst = (float4*)(g_w + (size_t)wsel * DIM * DIM) + off;
    }
    float4 v = *src;
    v.x = rnd(v.x); v.y = rnd(v.y); v.z = rnd(v.z); v.w = rnd(v.w);
    *dst = v;
}

// ---------------------------------------------------------------------------
// GEMM: C = A[8192,512] @ W[512,512] + bias. cp.async double-buffered.
// (unchanged from R5 — passing & adequate)
// ---------------------------------------------------------------------------
#define PAK 36
#define PBN 136
#define ASF (128*PAK)
#define BSF (32*PBN)
#define GEMM_SMEM ((2*ASF + 2*BSF) * 4)

__device__ __forceinline__ void gemm_body(
    const float* __restrict__ A, const float* __restrict__ W,
    const float* __restrict__ bias, float* __restrict__ dst,
    float oscale, int mode)
{
    extern __shared__ float sg[];
    float* Asf[2] = { sg, sg + ASF };
    float* Bsf[2] = { sg + 2*ASF, sg + 2*ASF + BSF };
    uint32_t asb[2] = { smem_u32(Asf[0]), smem_u32(Asf[1]) };
    uint32_t bsb[2] = { smem_u32(Bsf[0]), smem_u32(Bsf[1]) };

    const int tid = threadIdx.x;
    const int w = tid >> 5, t4 = tid & 3, tg = (tid & 31) >> 2;
    const int wm = (w & 3) * 32, wn = (w >> 2) * 64;
    const int bm = blockIdx.y * 128, bn = blockIdx.x * 128;

    int amr[4], af4[4], bkr[4], bf4[4];
#pragma unroll
    for (int i = 0; i < 4; ++i) {
        const int c = tid + i * 256;
        amr[i] = c >> 3;  af4[i] = (c & 7) << 2;
        bkr[i] = c >> 5;  bf4[i] = (c & 31) << 2;
    }

#define G_ISSUE(kc, bb)                                                         \
    {                                                                           \
        _Pragma("unroll")                                                       \
        for (int i = 0; i < 4; ++i)                                             \
            cpa(asb[bb] + (amr[i] * PAK + af4[i]) * 4,                          \
                A + (size_t)(bm + amr[i]) * DIM + (kc) * 32 + af4[i]);          \
        _Pragma("unroll")                                                       \
        for (int i = 0; i < 4; ++i)                                             \
            cpa(bsb[bb] + (bkr[i] * PBN + bf4[i]) * 4,                          \
                W + (size_t)((kc) * 32 + bkr[i]) * DIM + bn + bf4[i]);          \
        CP_COMMIT();                                                            \
    }

    float acc[2][8][4];
#pragma unroll
    for (int mb = 0; mb < 2; ++mb)
#pragma unroll
        for (int nb = 0; nb < 8; ++nb)
#pragma unroll
            for (int i = 0; i < 4; ++i) acc[mb][nb][i] = 0.f;

    G_ISSUE(0, 0);
    for (int kc = 0; kc < 16; ++kc) {
        const int bb = kc & 1;
        if (kc < 15) G_ISSUE(kc + 1, bb ^ 1);
        if (kc < 15) { CP_WAIT(1); } else { CP_WAIT(0); }
        __syncthreads();

        const uint32_t* As = (const uint32_t*)Asf[bb];
        const uint32_t* Bs = (const uint32_t*)Bsf[bb];
#pragma unroll
        for (int ks = 0; ks < 4; ++ks) {
            const int k8 = ks * 8;
            uint32_t a[2][4];
#pragma unroll
            for (int mb = 0; mb < 2; ++mb) {
                const int m0 = wm + mb * 16 + tg;
                a[mb][0] = As[m0 * PAK + k8 + t4];
                a[mb][1] = As[(m0 + 8) * PAK + k8 + t4];
                a[mb][2] = As[m0 * PAK + k8 + t4 + 4];
                a[mb][3] = As[(m0 + 8) * PAK + k8 + t4 + 4];
            }
#pragma unroll
            for (int nb = 0; nb < 8; ++nb) {
                uint32_t bf[2];
                const int n0 = wn + nb * 8 + tg;
                bf[0] = Bs[(k8 + t4) * PBN + n0];
                bf[1] = Bs[(k8 + t4 + 4) * PBN + n0];
                mma8(acc[0][nb], a[0], bf);
                mma8(acc[1][nb], a[1], bf);
            }
        }
        __syncthreads();
    }

#pragma unroll
    for (int mb = 0; mb < 2; ++mb)
#pragma unroll
        for (int nb = 0; nb < 8; ++nb)
#pragma unroll
            for (int half = 0; half < 2; ++half) {
                const int m = bm + wm + mb * 16 + tg + half * 8;
                const int n = bn + wn + nb * 8 + 2 * t4;
                float vx = (acc[mb][nb][half * 2 + 0] + bias[n]) * oscale;
                float vy = (acc[mb][nb][half * 2 + 1] + bias[n + 1]) * oscale;
                if (mode == 3) {
                    float2 o; o.x = vx; o.y = vy;
                    *(float2*)(dst + (size_t)m * DIM + n) = o;
                } else {
                    const int b = m >> 11, s = m & (SEQ - 1);
                    const int h = n >> 6, d = n & 63;
                    if (mode == 2) {
                        float2 o; o.x = rnd(vx); o.y = rnd(vy);
                        *(float2*)(dst + ((size_t)(b * NH + h) * SEQ + s) * DHD + d) = o;
                    } else {
                        float* base = dst + ((size_t)(b * NH + h) * DHD + d) * SEQ + s;
                        base[0]   = rnd(vx);
                        base[SEQ] = rnd(vy);
                    }
                }
            }
}

__global__ __launch_bounds__(256, 2) void qkv_kernel(
    const float* __restrict__ bq, const float* __restrict__ bk,
    const float* __restrict__ bv)
{
    const int z = blockIdx.z;
    const float* W = g_w + (size_t)z * DIM * DIM;
    const float* bias; float* dst; float sc = 1.f;
    if (z == 0)      { bias = bq; dst = g_qT; sc = QSCALE; }
    else if (z == 1) { bias = bk; dst = g_kT; }
    else             { bias = bv; dst = g_v; }
    gemm_body(g_x, W, bias, dst, sc, z);
}

__global__ __launch_bounds__(256, 2) void out_kernel(
    const float* __restrict__ bhp, float* __restrict__ out)
{
    gemm_body(g_att, g_w + 3ull * DIM * DIM, bhp, out, 1.f, 3);
}

// ---------------------------------------------------------------------------
// Fused flash attention v2: 128 threads (4 warps), each warp owns 32 q-rows
// (two m16 tiles) -> B-fragment smem traffic halved vs 8x16 layout.
// Q fragments persistent in regs (loaded from gmem in prologue, no Q smem).
// K/V double-buffered cp.async; P tile [q=128][k=64] pitch 68.
// ---------------------------------------------------------------------------
#define PKV  72
#define PPS  68           // >= 64 cols; 68 % 32 == 4 -> conflict-free PV A-frag loads
#define KVF  (64*PKV)     // 4608 floats per tile buffer
#define PSF2 (128*PPS)    // 8704 floats
#define ATTN_SMEM ((4*KVF + PSF2) * 4)   // 108,544 B -> 2 CTA/SM (217 KB < 228 KB)

__global__ __launch_bounds__(128, 2) void attn_kernel()
{
    extern __shared__ float sa[];
    float* Ksf[2] = { sa, sa + KVF };
    float* Vsf[2] = { sa + 2*KVF, sa + 3*KVF };
    float* Psf    = sa + 4*KVF;
    uint32_t ksb[2] = { smem_u32(Ksf[0]), smem_u32(Ksf[1]) };
    uint32_t vsb[2] = { smem_u32(Vsf[0]), smem_u32(Vsf[1]) };

    const int tid = threadIdx.x;
    const int w = tid >> 5, t4 = tid & 3, tg = (tid & 31) >> 2;
    const int wm = w * 32;
    const int h = blockIdx.y, b = blockIdx.z;
    const int qbase = blockIdx.x * 128;

    const float* qT = g_qT + (size_t)(b * NH + h) * DHD * SEQ;   // [d][s]
    const float* kT = g_kT + (size_t)(b * NH + h) * DHD * SEQ;   // [d][s]
    const float* vg = g_v  + (size_t)(b * NH + h) * SEQ * DHD;   // [s][d]

    int kvr[8], kvf[8];
#pragma unroll
    for (int i = 0; i < 8; ++i) {
        const int c = tid + i * 128;
        kvr[i] = c >> 4; kvf[i] = (c & 15) << 2;
    }

#define A_ISSUE(kt, bb)                                                          \
    {                                                                            \
        _Pragma("unroll")                                                        \
        for (int i = 0; i < 8; ++i)                                              \
            cpa(ksb[bb] + (kvr[i] * PKV + kvf[i]) * 4,                           \
                kT + (size_t)kvr[i] * SEQ + (kt) * 64 + kvf[i]);                 \
        _Pragma("unroll")                                                        \
        for (int i = 0; i < 8; ++i)                                              \
            cpa(vsb[bb] + (kvr[i] * PKV + kvf[i]) * 4,                           \
                vg + (size_t)((kt) * 64 + kvr[i]) * DHD + kvf[i]);               \
        CP_COMMIT();                                                             \
    }

    A_ISSUE(0, 0);

    // Persistent Q fragments: 8 ks x 2 m-tiles x 4 regs (one-time gmem reads;
    // g_qT already tf32-rounded and pre-scaled into the log2 domain)
    uint32_t qa[8][2][4];
#pragma unroll
    for (int ks = 0; ks < 8; ++ks) {
        const int d0 = ks * 8 + t4;
#pragma unroll
        for (int mt = 0; mt < 2; ++mt) {
            const int q0 = qbase + wm + mt * 16 + tg;
            qa[ks][mt][0] = __float_as_uint(qT[(size_t)d0 * SEQ + q0]);
            qa[ks][mt][1] = __float_as_uint(qT[(size_t)d0 * SEQ + q0 + 8]);
            qa[ks][mt][2] = __float_as_uint(qT[(size_t)(d0 + 4) * SEQ + q0]);
            qa[ks][mt][3] = __float_as_uint(qT[(size_t)(d0 + 4) * SEQ + q0 + 8]);
        }
    }

    CP_WAIT(0);
    __syncthreads();   // tile 0 ready

    float oc[2][8][4];
#pragma unroll
    for (int mt = 0; mt < 2; ++mt)
#pragma unroll
        for (int nb = 0; nb < 8; ++nb)
#pragma unroll
            for (int i = 0; i < 4; ++i) oc[mt][nb][i] = 0.f;
    float mrow[2][2], lrow[2][2];
#pragma unroll
    for (int mt = 0; mt < 2; ++mt) {
        mrow[mt][0] = -1e30f; mrow[mt][1] = -1e30f;
        lrow[mt][0] = 0.f;    lrow[mt][1] = 0.f;
    }

    for (int kt = 0; kt < SEQ / 64; ++kt) {
        const int bb = kt & 1;
        if (kt < SEQ / 64 - 1) A_ISSUE(kt + 1, bb ^ 1);
        if (kt < SEQ / 64 - 1) { CP_WAIT(1); } else { CP_WAIT(0); }
        __syncthreads();

        const uint32_t* Ks = (const uint32_t*)Ksf[bb];
        const uint32_t* Vs = (const uint32_t*)Vsf[bb];
        uint32_t* Ps = (uint32_t*)Psf;

        // ---- S = Q K^T : both m-tiles share every B fragment ----
        float sc[2][8][4];
#pragma unroll
        for (int mt = 0; mt < 2; ++mt)
#pragma unroll
            for (int nb = 0; nb < 8; ++nb)
#pragma unroll
                for (int i = 0; i < 4; ++i) sc[mt][nb][i] = 0.f;
#pragma unroll
        for (int ks = 0; ks < 8; ++ks) {
            const int k8 = ks * 8;
#pragma unroll
            for (int nb = 0; nb < 8; ++nb) {
                uint32_t bf[2];
                bf[0] = Ks[(k8 + t4) * PKV + nb * 8 + tg];
                bf[1] = Ks[(k8 + t4 + 4) * PKV + nb * 8 + tg];
                mma8(sc[0][nb], qa[ks][0], bf);
                mma8(sc[1][nb], qa[ks][1], bf);
            }
        }

        // ---- online softmax (exp2 domain) ----
#pragma unroll
        for (int mt = 0; mt < 2; ++mt) {
            float mx0 = sc[mt][0][0], mx1 = sc[mt][0][2];
#pragma unroll
            for (int nb = 0; nb < 8; ++nb) {
                mx0 = fmaxf(mx0, fmaxf(sc[mt][nb][0], sc[mt][nb][1]));
                mx1 = fmaxf(mx1, fmaxf(sc[mt][nb][2], sc[mt][nb][3]));
            }
            mx0 = fmaxf(mx0, __shfl_xor_sync(~0u, mx0, 1));
            mx0 = fmaxf(mx0, __shfl_xor_sync(~0u, mx0, 2));
            mx1 = fmaxf(mx1, __shfl_xor_sync(~0u, mx1, 1));
            mx1 = fmaxf(mx1, __shfl_xor_sync(~0u, mx1, 2));
            const float nm0 = fmaxf(mrow[mt][0], mx0);
            const float nm1 = fmaxf(mrow[mt][1], mx1);
            const float cr0 = ex2(mrow[mt][0] - nm0);
            const float cr1 = ex2(mrow[mt][1] - nm1);
            mrow[mt][0] = nm0; mrow[mt][1] = nm1;
            float s0 = 0.f, s1 = 0.f;
#pragma unroll
            for (int nb = 0; nb < 8; ++nb) {
                sc[mt][nb][0] = ex2(sc[mt][nb][0] - nm0); s0 += sc[mt][nb][0];
                sc[mt][nb][1] = ex2(sc[mt][nb][1] - nm0); s0 += sc[mt][nb][1];
                sc[mt][nb][2] = ex2(sc[mt][nb][2] - nm1); s1 += sc[mt][nb][2];
                sc[mt][nb][3] = ex2(sc[mt][nb][3] - nm1); s1 += sc[mt][nb][3];
            }
            s0 += __shfl_xor_sync(~0u, s0, 1); s0 += __shfl_xor_sync(~0u, s0, 2);
            s1 += __shfl_xor_sync(~0u, s1, 1); s1 += __shfl_xor_sync(~0u, s1, 2);
            lrow[mt][0] = lrow[mt][0] * cr0 + s0;
            lrow[mt][1] = lrow[mt][1] * cr1 + s1;
#pragma unroll
            for (int nb = 0; nb < 8; ++nb) {
                oc[mt][nb][0] *= cr0; oc[mt][nb][1] *= cr0;
                oc[mt][nb][2] *= cr1; oc[mt][nb][3] *= cr1;
            }
        }

        // ---- P -> smem [q][k] pitch 68, float2 stores (warp-local rows) ----
#pragma unroll
        for (int mt = 0; mt < 2; ++mt)
#pragma unroll
            for (int nb = 0; nb < 8; ++nb) {
                const int row0 = wm + mt * 16 + tg;
                const int col  = nb * 8 + 2 * t4;
                uint2 u0; u0.x = f2tf(sc[mt][nb][0]); u0.y = f2tf(sc[mt][nb][1]);
                uint2 u1; u1.x = f2tf(sc[mt][nb][2]); u1.y = f2tf(sc[mt][nb][3]);
                *(uint2*)&Ps[row0 * PPS + col]       = u0;
                *(uint2*)&Ps[(row0 + 8) * PPS + col] = u1;
            }
        __syncwarp();

        // ---- O += P V : both m-tiles share every V fragment ----
#pragma unroll
        for (int ks = 0; ks < 8; ++ks) {
            const int k8 = ks * 8;
            uint32_t pa[2][4];
#pragma unroll
            for (int mt = 0; mt < 2; ++mt) {
                const int row0 = wm + mt * 16 + tg;
                pa[mt][0] = Ps[row0 * PPS + k8 + t4];
                pa[mt][1] = Ps[(row0 + 8) * PPS + k8 + t4];
                pa[mt][2] = Ps[row0 * PPS + k8 + t4 + 4];
                pa[mt][3] = Ps[(row0 + 8) * PPS + k8 + t4 + 4];
            }
#pragma unroll
            for (int nb = 0; nb < 8; ++nb) {
                uint32_t bf[2];
                bf[0] = Vs[(k8 + t4) * PKV + nb * 8 + tg];
                bf[1] = Vs[(k8 + t4 + 4) * PKV + nb * 8 + tg];
                mma8(oc[0][nb], pa[0], bf);
                mma8(oc[1][nb], pa[1], bf);
            }
        }
        __syncthreads();   // release buffer bb
    }

#pragma unroll
    for (int mt = 0; mt < 2; ++mt) {
        const float inv0 = 1.f / lrow[mt][0], inv1 = 1.f / lrow[mt][1];
        const int q0 = qbase + wm + mt * 16 + tg;
        float* og0 = g_att + ((size_t)b * SEQ + q0) * DIM + h * DHD;
        float* og1 = og0 + 8 * DIM;
#pragma unroll
        for (int nb = 0; nb < 8; ++nb) {
            const int d = nb * 8 + 2 * t4;
            float2 o0; o0.x = rnd(oc[mt][nb][0] * inv0); o0.y = rnd(oc[mt][nb][1] * inv0);
            float2 o1; o1.x = rnd(oc[mt][nb][2] * inv1); o1.y = rnd(oc[mt][nb][3] * inv1);
            *(float2*)(og0 + d) = o0;
            *(float2*)(og1 + d) = o1;
        }
    }
}

// ---------------------------------------------------------------------------
extern "C" void kernel_launch(void* const* d_in, const int* in_sizes, int n_in,
                              void* d_out, int out_size)
{
    const float* x  = (const float*)d_in[0];
    const float* Wq = (const float*)d_in[1];
    const float* bq = (const float*)d_in[2];
    const float* Wk = (const float*)d_in[3];
    const float* bk = (const float*)d_in[4];
    const float* Wv = (const float*)d_in[5];
    const float* bv = (const float*)d_in[6];
    const float* Wh = (const float*)d_in[7];
    const float* bh = (const float*)d_in[8];
    float* out = (float*)d_out;

    cudaFuncSetAttribute(qkv_kernel, cudaFuncAttributeMaxDynamicSharedMemorySize, GEMM_SMEM);
    cudaFuncSetAttribute(out_kernel, cudaFuncAttributeMaxDynamicSharedMemorySize, GEMM_SMEM);
    cudaFuncSetAttribute(attn_kernel, cudaFuncAttributeMaxDynamicSharedMemorySize, ATTN_SMEM);

    // 0. tf32-round inputs + weights
    prep_kernel<<<(XF4 + 4 * WF4 + 255) / 256, 256>>>(x, Wq, Wk, Wv, Wh);

    // 1. QKV projections (Q pre-scaled into log2 domain; Q/K stored [b,h,d,s])
    qkv_kernel<<<dim3(4, 64, 3), 256, GEMM_SMEM>>>(bq, bk, bv);

    // 2. Fused flash attention (4 warps x 32 q-rows)
    attn_kernel<<<dim3(SEQ / 128, NH, NB), 128, ATTN_SMEM>>>();

    // 3. Output projection
    out_kernel<<<dim3(4, 64), 256, GEMM_SMEM>>>(bh, out);
}